// round 7
// baseline (speedup 1.0000x reference)
#include <cuda_runtime.h>
#include <cstdint>

#define B_DIM 32
#define S_LEN 2048
#define I_DIM 256
#define H_DIM 256

// k-split for the recurrence weights: [0, K_REG) in registers, rest streamed.
#define K_REG 176
#define K_TAIL (H_DIM - K_REG)            // 80 floats = 20 x 16B loads

// ---------------------------------------------------------------------------
// helpers
// ---------------------------------------------------------------------------
__device__ __forceinline__ unsigned long long ffma2(unsigned long long a,
                                                    unsigned long long b,
                                                    unsigned long long c) {
    unsigned long long d;
    asm("fma.rn.f32x2 %0, %1, %2, %3;" : "=l"(d) : "l"(a), "l"(b), "l"(c));
    return d;
}
__device__ __forceinline__ unsigned long long add2(unsigned long long a,
                                                   unsigned long long b) {
    unsigned long long d;
    asm("add.rn.f32x2 %0, %1, %2;" : "=l"(d) : "l"(a), "l"(b));
    return d;
}
__device__ __forceinline__ unsigned long long pack2(float x, float y) {
    unsigned long long d;
    asm("mov.b64 %0, {%1, %2};" : "=l"(d) : "f"(x), "f"(y));
    return d;
}
__device__ __forceinline__ float2 unpack2(unsigned long long v) {
    float2 r;
    asm("mov.b64 {%0, %1}, %2;" : "=f"(r.x), "=f"(r.y) : "l"(v));
    return r;
}
// 16B global load, forced to re-issue every step (volatile: no CSE/hoist),
// .nc -> L1-resident read-only path.
__device__ __forceinline__ void ldg16_v(const void* p, unsigned long long& a,
                                        unsigned long long& b) {
    asm volatile("ld.global.nc.v2.u64 {%0, %1}, [%2];"
                 : "=l"(a), "=l"(b) : "l"(p));
}
__device__ __forceinline__ float tanh_fast(float x) {
    float r;
    asm("tanh.approx.f32 %0, %1;" : "=f"(r) : "f"(x));
    return r;
}

// ---------------------------------------------------------------------------
// Kernel 1: xw[b,s,h] = x[b,s,:] . Wx_w[h,:] + Wx_b[h]  (into outputs region)
// ---------------------------------------------------------------------------
__global__ __launch_bounds__(256, 2)
void xw_gemm_kernel(const float* __restrict__ A, const float* __restrict__ W,
                    const float* __restrict__ bias, float* __restrict__ C) {
    __shared__ __align__(16) float As[16][128];
    __shared__ __align__(16) float Bs[16][128];

    const int tid = threadIdx.x;
    const int tx = tid & 15;
    const int ty = tid >> 4;
    const long bm = (long)blockIdx.x * 128;
    const long bn = (long)blockIdx.y * 128;

    const float* Ab = A + bm * I_DIM;
    const float* Wb = W + bn * I_DIM;

    unsigned long long acc[8][4];
#pragma unroll
    for (int i = 0; i < 8; i++)
#pragma unroll
        for (int j = 0; j < 4; j++) acc[i][j] = 0ull;

    for (int k0 = 0; k0 < I_DIM; k0 += 16) {
#pragma unroll
        for (int f = tid; f < 512; f += 256) {
            int row = f >> 2, kq = f & 3;
            float4 va = *(const float4*)(Ab + (long)row * I_DIM + k0 + kq * 4);
            As[kq * 4 + 0][row] = va.x; As[kq * 4 + 1][row] = va.y;
            As[kq * 4 + 2][row] = va.z; As[kq * 4 + 3][row] = va.w;
            float4 vw = *(const float4*)(Wb + (long)row * I_DIM + k0 + kq * 4);
            Bs[kq * 4 + 0][row] = vw.x; Bs[kq * 4 + 1][row] = vw.y;
            Bs[kq * 4 + 2][row] = vw.z; Bs[kq * 4 + 3][row] = vw.w;
        }
        __syncthreads();
#pragma unroll
        for (int k = 0; k < 16; k++) {
            const float4* As4 = (const float4*)&As[k][0];
            const ulonglong2* Bs2 = (const ulonglong2*)&Bs[k][0];
            float4 a0 = As4[ty * 2], a1 = As4[ty * 2 + 1];
            ulonglong2 bA = Bs2[tx * 2], bB = Bs2[tx * 2 + 1];
            unsigned long long bp[4] = {bA.x, bA.y, bB.x, bB.y};
            float av[8] = {a0.x, a0.y, a0.z, a0.w, a1.x, a1.y, a1.z, a1.w};
#pragma unroll
            for (int i = 0; i < 8; i++) {
                unsigned long long ap = pack2(av[i], av[i]);
#pragma unroll
                for (int j = 0; j < 4; j++) acc[i][j] = ffma2(ap, bp[j], acc[i][j]);
            }
        }
        __syncthreads();
    }

    float bv[8];
#pragma unroll
    for (int j = 0; j < 8; j++) bv[j] = bias[bn + tx * 8 + j];
#pragma unroll
    for (int i = 0; i < 8; i++) {
        long m = bm + ty * 8 + i;
        float* Crow = C + m * (long)H_DIM + bn + tx * 8;
        float2 c0 = unpack2(acc[i][0]), c1 = unpack2(acc[i][1]);
        float2 c2 = unpack2(acc[i][2]), c3 = unpack2(acc[i][3]);
        *(float4*)(Crow)     = make_float4(c0.x + bv[0], c0.y + bv[1], c1.x + bv[2], c1.y + bv[3]);
        *(float4*)(Crow + 4) = make_float4(c2.x + bv[4], c2.y + bv[5], c3.x + bv[6], c3.y + bv[7]);
    }
}

// ---------------------------------------------------------------------------
// Kernel 2: recurrence, SINGLE CTA per batch row (no cluster, no mbarrier).
// 256 threads; thread j owns output column j (full k range, NO reduction).
// Wh row j: k in [0,K_REG) lives in registers; k in [K_REG,256) is re-loaded
// every step via volatile ld.global.nc (L1-resident, h-independent => issued
// early, latency hidden under the main FMA stream). h ping-pongs in smem;
// exactly one __syncthreads per step.
// ---------------------------------------------------------------------------
__global__ __launch_bounds__(256, 1)
void srnn_recur_kernel(const float* __restrict__ Wh, float* __restrict__ out) {
    __shared__ __align__(16) float hbuf[2][H_DIM];

    const int j   = threadIdx.x;      // output column 0..255
    const int row = blockIdx.x;       // batch row

    const float* wrow = Wh + (long)j * H_DIM;

    // --- preload k in [0, K_REG) : 88 f32x2 pairs in registers ---
    unsigned long long w[K_REG / 2];
    {
        const ulonglong2* wr2 = (const ulonglong2*)wrow;
#pragma unroll
        for (int u = 0; u < K_REG / 4; u++) {
            ulonglong2 v = wr2[u];
            w[2 * u]     = v.x;
            w[2 * u + 1] = v.y;
        }
    }
    const char* wtail = (const char*)(wrow + K_REG);   // 80 floats = 20 x 16B

    hbuf[0][j] = 0.0f;               // h0 = 0
    __syncthreads();

    float* xwp = out + (long)row * S_LEN * H_DIM + j;
    float xw_next = xwp[0];

    int p = 0;
    for (int step = 0; step < S_LEN; step++) {
        float xw_cur = xw_next;
        if (step + 1 < S_LEN)
            xw_next = xwp[(long)(step + 1) * H_DIM];

        const ulonglong2* h4 = (const ulonglong2*)&hbuf[p][0];

        unsigned long long a0 = 0ull, a1 = 0ull, a2 = 0ull, a3 = 0ull;

        // ---- wave A of tail-weight loads (h-independent, L1 hits) ----
        unsigned long long twA[20];
#pragma unroll
        for (int i = 0; i < 10; i++)
            ldg16_v(wtail + i * 16, twA[2 * i], twA[2 * i + 1]);

        // ---- main register-weight FMAs: k in [0, K_REG) ----
#pragma unroll
        for (int u = 0; u < K_REG / 4; u++) {          // 44 iters, 2 pairs each
            ulonglong2 hv = h4[u];
            a0 = ffma2(hv.x, w[2 * u], a0);
            a1 = ffma2(hv.y, w[2 * u + 1], a1);
        }

        // ---- tail wave A FMAs: k in [K_REG, K_REG+40) ----
#pragma unroll
        for (int i = 0; i < 10; i++) {
            ulonglong2 hv = h4[K_REG / 4 + i];         // h pairs k=176+4i..
            a2 = ffma2(hv.x, twA[2 * i], a2);
            a3 = ffma2(hv.y, twA[2 * i + 1], a3);
        }

        // ---- wave B of tail loads + FMAs: k in [K_REG+40, 256) ----
        unsigned long long twB[20];
#pragma unroll
        for (int i = 0; i < 10; i++)
            ldg16_v(wtail + 160 + i * 16, twB[2 * i], twB[2 * i + 1]);
#pragma unroll
        for (int i = 0; i < 10; i++) {
            ulonglong2 hv = h4[(K_REG + 40) / 4 + i];
            a2 = ffma2(hv.x, twB[2 * i], a2);
            a3 = ffma2(hv.y, twB[2 * i + 1], a3);
        }

        unsigned long long s = add2(add2(a0, a1), add2(a2, a3));
        float2 f = unpack2(s);
        float v = tanh_fast(f.x + f.y + xw_cur);

        hbuf[p ^ 1][j] = v;                    // next h
        xwp[(long)step * H_DIM] = v;           // in-place output [row,step,j]
        if (step == S_LEN - 1)
            out[(long)B_DIM * S_LEN * H_DIM + (long)row * H_DIM + j] = v;

        __syncthreads();                       // the ONLY sync per step
        p ^= 1;
    }
}

// ---------------------------------------------------------------------------
// Launch
// ---------------------------------------------------------------------------
extern "C" void kernel_launch(void* const* d_in, const int* in_sizes, int n_in,
                              void* d_out, int out_size) {
    const float* x    = (const float*)d_in[0];  // [B,S,I]
    const float* Wx_w = (const float*)d_in[1];  // [H,I]
    const float* Wx_b = (const float*)d_in[2];  // [H]
    const float* Wh_w = (const float*)d_in[3];  // [H,H]
    float* out = (float*)d_out;                 // [B,S,H] ++ [B,H]

    dim3 g1((B_DIM * S_LEN) / 128, H_DIM / 128);
    xw_gemm_kernel<<<g1, 256>>>(x, Wx_w, Wx_b, out);

    srnn_recur_kernel<<<B_DIM, H_DIM>>>(Wh_w, out);
}